// round 7
// baseline (speedup 1.0000x reference)
#include <cuda_runtime.h>
#include <math.h>

#define N    512
#define RT   32
#define JT   32
#define BUP2 33     // Bu row stride in ulls

typedef unsigned long long ull;

__device__ float    g_sq[N * N];
__device__ float    g_Ls[N];
__device__ int      g_perm[N];
__device__ double   g_partial[256];
__device__ unsigned g_count;     // zero-init; reset by last loss block each launch

__device__ __forceinline__ int fbase(int i){
  return (i < 256) ? (i * 512) : ((i - 256) * 512 + 256);
}
__device__ __forceinline__ void fma2(ull &acc, ull a, ull b){
  asm("fma.rn.f32x2 %0, %1, %2, %0;" : "+l"(acc) : "l"(a), "l"(b));
}
__device__ __forceinline__ float2 u2f(ull x){
  float2 f; asm("mov.b64 {%0,%1}, %2;" : "=f"(f.x), "=f"(f.y) : "l"(x)); return f;
}
__device__ __forceinline__ ull f2u(float a, float b){
  ull r; asm("mov.b64 %0, {%1,%2};" : "=l"(r) : "f"(a), "f"(b)); return r;
}
__device__ __forceinline__ float fsqrt_ap(float x){
  float r; asm("sqrt.approx.f32 %0, %1;" : "=f"(r) : "f"(x)); return r;
}
__device__ __forceinline__ float ex2_ap(float x){
  float r; asm("ex2.approx.f32 %0, %1;" : "=f"(r) : "f"(x)); return r;
}
__device__ __forceinline__ float lg2_ap(float x){
  float r; asm("lg2.approx.f32 %0, %1;" : "=f"(r) : "f"(x)); return r;
}

struct GSmem {
  ull   Au[RT][128];      // 32 KB
  ull   Bu[128][BUP2];    // ~33.8 KB
  float nrmA[RT];
  float nrmB[JT];
  float lab[256];
};

// ------------- kernel 1: 32x32 Gram tiles, 512 threads (+ block 0: label sort) --------
__global__ void __launch_bounds__(512) dist_kernel(const float* __restrict__ feat,
                                                   const float* __restrict__ labels)
{
  extern __shared__ char raw[];
  GSmem& S = *(GSmem*)raw;

  const int t = threadIdx.x, lane = t & 31, w = t >> 5;
  const int bj = blockIdx.x & 15, bi = blockIdx.x >> 4;
  const int r0 = bi * RT, j0 = bj * JT;

  if (t < 256) S.lab[t] = labels[t];

  // A tile [32 rows][256 k] natural layout (k-pairs in ull halves): 4 float4/thread
#pragma unroll
  for (int p = 0; p < 4; p++){
    const int idx = t + 512 * p;
    const int row = idx >> 6, c = idx & 63;
    ((float4*)S.Au[row])[c] = *(const float4*)(feat + fbase(r0 + row) + 4 * c);
  }
  // B tile transposed: Bu[d2][j] = {f[j][2d2], f[j][2d2+1]}: 4 float4/thread
  {
    const int j = t >> 4, u = t & 15;
#pragma unroll
    for (int q = 0; q < 4; q++){
      const float4 v = *(const float4*)(feat + fbase(j0 + j) + 64 * q + 4 * u);
      const int d2 = 32 * q + 2 * u;
      S.Bu[d2    ][j] = f2u(v.x, v.y);
      S.Bu[d2 + 1][j] = f2u(v.z, v.w);
    }
  }
  __syncthreads();

  // block 0: global label rank sort
  if (blockIdx.x == 0 && t < 256){
    const float v = S.lab[t];
    int r = 0;
#pragma unroll 8
    for (int j = 0; j < 256; j++){
      const float u = S.lab[j];
      r += (u < v) | ((u == v) & (j < t));
    }
    g_Ls[2*r] = v;  g_Ls[2*r+1] = v;
    g_perm[2*r] = t; g_perm[2*r+1] = t + 256;
  }

  // norms
  if (t < 32){
    ull a0 = 0, a1 = 0;
#pragma unroll 16
    for (int d2 = 0; d2 < 128; d2 += 2){
      fma2(a0, S.Au[t][d2],   S.Au[t][d2]);
      fma2(a1, S.Au[t][d2+1], S.Au[t][d2+1]);
    }
    const float2 f0 = u2f(a0), f1 = u2f(a1);
    S.nrmA[t] = (f0.x + f0.y) + (f1.x + f1.y);
  } else if (t < 64){
    const int jn = t - 32;
    ull a0 = 0, a1 = 0;
#pragma unroll 16
    for (int d2 = 0; d2 < 128; d2 += 2){
      fma2(a0, S.Bu[d2  ][jn], S.Bu[d2  ][jn]);
      fma2(a1, S.Bu[d2+1][jn], S.Bu[d2+1][jn]);
    }
    const float2 f0 = u2f(a0), f1 = u2f(a1);
    S.nrmB[jn] = (f0.x + f0.y) + (f1.x + f1.y);
  }

  // main: warp w (0..15) -> rows 2w, 2w+1; lane -> j = lane
  ull acc0 = 0, acc1 = 0;
#pragma unroll 8
  for (int d2 = 0; d2 < 128; d2 += 2){
    const ull b0 = S.Bu[d2    ][lane];
    const ull b1 = S.Bu[d2 + 1][lane];
    const ulonglong2 av0 = *(const ulonglong2*)&S.Au[2*w    ][d2];  // broadcast
    const ulonglong2 av1 = *(const ulonglong2*)&S.Au[2*w + 1][d2];  // broadcast
    fma2(acc0, av0.x, b0);  fma2(acc0, av0.y, b1);
    fma2(acc1, av1.x, b0);  fma2(acc1, av1.y, b1);
  }
  __syncthreads();   // norms visible

  const float nj = S.nrmB[lane];
  {
    const float2 gA = u2f(acc0), gB = u2f(acc1);
    g_sq[(r0 + 2*w    ) * N + j0 + lane] = S.nrmA[2*w    ] + nj - 2.f * (gA.x + gA.y);
    g_sq[(r0 + 2*w + 1) * N + j0 + lane] = S.nrmA[2*w + 1] + nj - 2.f * (gB.x + gB.y);
  }
}

// -- kernel 2: loss; block b handles rows b, b+256 (identical labels); 512 threads ----
__global__ void __launch_bounds__(512) loss_kernel(const float* __restrict__ labels,
                                                   float* __restrict__ out)
{
  __shared__ float  s_Ls[N];
  __shared__ int    s_perm[N];
  __shared__ float  s_lab[256];
  __shared__ float  s_sq0[N], s_sq1[N];
  __shared__ double s_P0[N], s_P1[N];
  __shared__ double s_w0[16], s_w1[16];
  __shared__ double s_red[16];
  __shared__ bool   s_last;

  const int t = threadIdx.x, lane = t & 31, w = t >> 5;
  const int i0 = blockIdx.x, i1 = blockIdx.x + 256;

  if (t < 256) s_lab[t] = labels[t];
  s_Ls[t]   = g_Ls[t];
  s_perm[t] = g_perm[t];
  s_sq0[t]  = g_sq[i0 * N + t];
  s_sq1[t]  = g_sq[i1 * N + t];
  __syncthreads();

  const float li = s_lab[i0 & 255];
  const float KE  = -0.72134752044448170f;   // -0.5 * log2(e)
  const float LN2 =  0.69314718055994531f;

  // sorted position x = t; both rows
  const int j = s_perm[t];
  const float d0 = (j == i0) ? 0.f : fsqrt_ap(fmaxf(s_sq0[j], 0.f));
  const float d1 = (j == i1) ? 0.f : fsqrt_ap(fmaxf(s_sq1[j], 0.f));
  const float e0 = (j == i0) ? 1.f : ex2_ap(KE * d0);
  const float e1 = (j == i1) ? 1.f : ex2_ap(KE * d1);

  // two interleaved warp-shuffle inclusive scans (double), 1 elem/thread
  double sc0 = (double)e0, sc1 = (double)e1;
#pragma unroll
  for (int o = 1; o < 32; o <<= 1){
    const double v0 = __shfl_up_sync(0xffffffffu, sc0, o);
    const double v1 = __shfl_up_sync(0xffffffffu, sc1, o);
    if (lane >= o){ sc0 += v0; sc1 += v1; }
  }
  if (lane == 31){ s_w0[w] = sc0; s_w1[w] = sc1; }
  __syncthreads();
  if (w == 0 && lane < 16){
    double v = s_w0[lane];
#pragma unroll
    for (int o = 1; o < 16; o <<= 1){
      const double u = __shfl_up_sync(0xffffu, v, o);
      if (lane >= o) v += u;
    }
    s_w0[lane] = v;
  } else if (w == 1 && lane < 16){
    double v = s_w1[lane];
#pragma unroll
    for (int o = 1; o < 16; o <<= 1){
      const double u = __shfl_up_sync(0xffffu, v, o);
      if (lane >= o) v += u;
    }
    s_w1[lane] = v;
  }
  __syncthreads();
  const double q0 = ((w > 0) ? s_w0[w - 1] : 0.0) + sc0;
  const double q1 = ((w > 0) ? s_w1[w - 1] : 0.0) + sc1;
  s_P0[t] = q0;
  s_P1[t] = q1;
  __syncthreads();
  const double total0 = s_P0[N - 1], total1 = s_P1[N - 1];

  // il: first sorted pos with Ls >= li (label-only, shared by both rows)
  int lo = 0, len = N;
  while (len){ const int h = len >> 1, m = lo + h;
    if (s_Ls[m] < li){ lo = m + 1; len -= h + 1; } else len = h; }
  const int il = lo;

  // one k per thread; left/right boundary chains shared by both rows
  const int k = t;
  const float tk = fabsf(s_lab[k & 255] - li);
  int a = 0, la = il + 1, c = il, lc = N - il;
#pragma unroll 1
  for (int s = 0; s < 10; s++){
    if (la){ const int h = la >> 1, m = a + h;
      if (!(fabsf(s_Ls[m] - li) < tk)){ a = m + 1; la -= h + 1; } else la = h; }
    if (lc){ const int h = lc >> 1, m = c + h;
      if ( (fabsf(s_Ls[m] - li) < tk)){ c = m + 1; lc -= h + 1; } else lc = h; }
  }

  float lgsum = 0.f;
  if (k != i0){
    const double neg = (tk == 0.f) ? (total0 - 1.0)
        : (total0 - (s_P0[c - 1] - (a > 0 ? s_P0[a - 1] : 0.0)));
    lgsum += lg2_ap((float)neg);
  }
  if (k != i1){
    const double neg = (tk == 0.f) ? (total1 - 1.0)
        : (total1 - (s_P1[c - 1] - (a > 0 ? s_P1[a - 1] : 0.0)));
    lgsum += lg2_ap((float)neg);
  }

  double acc = 0.5 * (double)(d0 + d1) + (double)(LN2 * lgsum);

#pragma unroll
  for (int o = 16; o; o >>= 1) acc += __shfl_xor_sync(0xffffffffu, acc, o);
  if (lane == 0) s_red[w] = acc;
  __syncthreads();
  if (w == 0){
    double v = (lane < 16) ? s_red[lane] : 0.0;
#pragma unroll
    for (int o = 8; o; o >>= 1) v += __shfl_xor_sync(0xffffffffu, v, o);
    if (lane == 0){
      g_partial[blockIdx.x] = v;
      __threadfence();
      s_last = (atomicAdd(&g_count, 1u) == 255u);
    }
  }
  __syncthreads();

  if (s_last){
    double v = (t < 256) ? *((volatile double*)&g_partial[t]) : 0.0;
#pragma unroll
    for (int o = 16; o; o >>= 1) v += __shfl_xor_sync(0xffffffffu, v, o);
    if (lane == 0) s_red[w] = v;
    __syncthreads();
    if (w == 0){
      double s = (lane < 16) ? s_red[lane] : 0.0;
#pragma unroll
      for (int o = 8; o; o >>= 1) s += __shfl_xor_sync(0xffffffffu, s, o);
      if (lane == 0){
        out[0] = (float)(s / (512.0 * 511.0));
        g_count = 0;
      }
    }
  }
}

extern "C" void kernel_launch(void* const* d_in, const int* in_sizes, int n_in,
                              void* d_out, int out_size)
{
  const float* feat   = (const float*)d_in[0];
  const float* labels = (const float*)d_in[1];
  float* out = (float*)d_out;

  cudaFuncSetAttribute(dist_kernel, cudaFuncAttributeMaxDynamicSharedMemorySize,
                       (int)sizeof(GSmem));
  dist_kernel<<<256, 512, sizeof(GSmem)>>>(feat, labels);
  loss_kernel<<<256, 512>>>(labels, out);
}

// round 8
// speedup vs baseline: 1.0195x; 1.0195x over previous
#include <cuda_runtime.h>
#include <math.h>

#define N 512

typedef unsigned long long ull;

__device__ float    g_sq[N * N];
__device__ float    g_Ls[N];
__device__ int      g_perm[N];
__device__ double   g_partial[256];
__device__ unsigned g_c1;     // grid-barrier arrive
__device__ unsigned g_c2;     // grid-barrier depart (resets c1,c2)
__device__ unsigned g_c3;     // final-reduce counter

__device__ __forceinline__ int fbase(int i){
  return (i < 256) ? (i * 512) : ((i - 256) * 512 + 256);
}
__device__ __forceinline__ void fma2(ull &acc, ull a, ull b){
  asm("fma.rn.f32x2 %0, %1, %2, %0;" : "+l"(acc) : "l"(a), "l"(b));
}
__device__ __forceinline__ float2 u2f(ull x){
  float2 f; asm("mov.b64 {%0,%1}, %2;" : "=f"(f.x), "=f"(f.y) : "l"(x)); return f;
}
__device__ __forceinline__ ull f2u(float a, float b){
  ull r; asm("mov.b64 %0, {%1,%2};" : "=l"(r) : "f"(a), "f"(b)); return r;
}
__device__ __forceinline__ float fsqrt_ap(float x){
  float r; asm("sqrt.approx.f32 %0, %1;" : "=f"(r) : "f"(x)); return r;
}
__device__ __forceinline__ float ex2_ap(float x){
  float r; asm("ex2.approx.f32 %0, %1;" : "=f"(r) : "f"(x)); return r;
}
__device__ __forceinline__ float lg2_ap(float x){
  float r; asm("lg2.approx.f32 %0, %1;" : "=f"(r) : "f"(x)); return r;
}

struct GS {                 // phase-1 layout
  ull   Au[32][128];        // A tile [row][k-pair]      32 KB
  ull   Bu[128][33];        // B tile [k-pair][j] padded ~33.8 KB
  float Cpart[32][33];      // k-split partials          ~4.2 KB
  float nrmA[32];
  float nrmB[32];
  float lab[256];
  int   rankcnt;
};
struct LS {                 // phase-2 layout
  float  Ls[N];  int perm[N];
  float  lab[256];
  float  sq0[N], sq1[N];
  double P0[N],  P1[N];
  double w0[16], w1[16];
  double red[16];
};
union USm { GS g; LS l; };

__global__ void __launch_bounds__(512, 2) rnc_all(const float* __restrict__ feat,
                                                  const float* __restrict__ labels,
                                                  float* __restrict__ out)
{
  extern __shared__ char raw[];
  USm& S = *(USm*)raw;

  const int t = threadIdx.x, lane = t & 31, w = t >> 5;
  const int b = blockIdx.x;
  const int bj = b & 15, bi = b >> 4;
  const int r0 = bi * 32, j0 = bj * 32;

  // ================= PHASE 1: distances (32x32 Gram tile, k-split) ============
  if (t < 256) S.g.lab[t] = labels[t];
  if (t == 0)  S.g.rankcnt = 0;

  // A tile [32 rows][256 k] natural layout (k-pairs in ull halves)
#pragma unroll
  for (int p = 0; p < 4; p++){
    const int idx = t + 512 * p;
    const int row = idx >> 6, c = idx & 63;
    ((float4*)S.g.Au[row])[c] = *(const float4*)(feat + fbase(r0 + row) + 4 * c);
  }
  // B tile transposed: Bu[d2][j] = {f[j][2d2], f[j][2d2+1]}
  {
    const int j = t >> 4, u = t & 15;
#pragma unroll
    for (int q = 0; q < 4; q++){
      const float4 v = *(const float4*)(feat + fbase(j0 + j) + 64 * q + 4 * u);
      const int d2 = 32 * q + 2 * u;
      S.g.Bu[d2    ][j] = f2u(v.x, v.y);
      S.g.Bu[d2 + 1][j] = f2u(v.z, v.w);
    }
  }
  __syncthreads();

  // distributed label rank: this block ranks label b (ballot + popc)
  if (t < 256){
    const float vb = S.g.lab[b];
    const float vt = S.g.lab[t];
    const bool pred = (vt < vb) || ((vt == vb) && (t < b));
    const unsigned bal = __ballot_sync(0xffffffffu, pred);
    if (lane == 0 && bal) atomicAdd(&S.g.rankcnt, __popc(bal));
  }

  // norms (full k): t<32 rows, 32<=t<64 js
  if (t < 32){
    ull a0 = 0, a1 = 0;
#pragma unroll 16
    for (int d2 = 0; d2 < 128; d2 += 2){
      fma2(a0, S.g.Au[t][d2],   S.g.Au[t][d2]);
      fma2(a1, S.g.Au[t][d2+1], S.g.Au[t][d2+1]);
    }
    const float2 f0 = u2f(a0), f1 = u2f(a1);
    S.g.nrmA[t] = (f0.x + f0.y) + (f1.x + f1.y);
  } else if (t < 64){
    const int jn = t - 32;
    ull a0 = 0, a1 = 0;
#pragma unroll 16
    for (int d2 = 0; d2 < 128; d2 += 2){
      fma2(a0, S.g.Bu[d2  ][jn], S.g.Bu[d2  ][jn]);
      fma2(a1, S.g.Bu[d2+1][jn], S.g.Bu[d2+1][jn]);
    }
    const float2 f0 = u2f(a0), f1 = u2f(a1);
    S.g.nrmB[jn] = (f0.x + f0.y) + (f1.x + f1.y);
  }

  // main: warp-half kh covers k-range, 4 rows per warp
  const int w2 = w & 7, kh = w >> 3;
  const int d2b = kh * 64;
  ull acc[4] = {0, 0, 0, 0};
#pragma unroll 8
  for (int s = 0; s < 64; s += 2){
    const int d2 = d2b + s;
    const ull b0 = S.g.Bu[d2    ][lane];
    const ull b1 = S.g.Bu[d2 + 1][lane];
#pragma unroll
    for (int rr = 0; rr < 4; rr++){
      const ulonglong2 av = *(const ulonglong2*)&S.g.Au[4*w2 + rr][d2];  // broadcast
      fma2(acc[rr], av.x, b0);
      fma2(acc[rr], av.y, b1);
    }
  }
  float p[4];
#pragma unroll
  for (int rr = 0; rr < 4; rr++){ const float2 g = u2f(acc[rr]); p[rr] = g.x + g.y; }
  if (kh == 1){
#pragma unroll
    for (int rr = 0; rr < 4; rr++) S.g.Cpart[4*w2 + rr][lane] = p[rr];
  }
  __syncthreads();   // Cpart, norms, rankcnt ready

  if (t == 0){
    const int r = S.g.rankcnt;
    const float vb = S.g.lab[b];
    g_Ls[2*r] = vb;   g_Ls[2*r + 1] = vb;
    g_perm[2*r] = b;  g_perm[2*r + 1] = b + 256;
  }
  if (kh == 0){
    const float nj = S.g.nrmB[lane];
#pragma unroll
    for (int rr = 0; rr < 4; rr++){
      const float ni = S.g.nrmA[4*w2 + rr];
      g_sq[(r0 + 4*w2 + rr) * N + j0 + lane] =
          ni + nj - 2.f * (p[rr] + S.g.Cpart[4*w2 + rr][lane]);
    }
  }

  // ================= GRID BARRIER (all 256 blocks co-resident) ================
  if (t == 0){
    __threadfence();
    atomicAdd(&g_c1, 1u);
    while (*(volatile unsigned*)&g_c1 < 256u) __nanosleep(64);
    __threadfence();
    const unsigned d = atomicAdd(&g_c2, 1u);
    if (d == 255u){           // unique last block through: reset for next replay
      g_c1 = 0u; g_c2 = 0u;
      __threadfence();
    }
  }
  __syncthreads();            // also separates smem union phases

  // ================= PHASE 2: loss for rows b and b+256 =======================
  const int i0 = b, i1 = b + 256;
  if (t < 256) S.l.lab[t] = labels[t];
  S.l.Ls[t]   = __ldcg(&g_Ls[t]);
  S.l.perm[t] = __ldcg(&g_perm[t]);
  S.l.sq0[t]  = __ldcg(&g_sq[i0 * N + t]);
  S.l.sq1[t]  = __ldcg(&g_sq[i1 * N + t]);
  __syncthreads();

  const float li  = S.l.lab[b];
  const float KE  = -0.72134752044448170f;   // -0.5 * log2(e)
  const float LN2 =  0.69314718055994531f;

  const int j = S.l.perm[t];
  const float d0 = (j == i0) ? 0.f : fsqrt_ap(fmaxf(S.l.sq0[j], 0.f));
  const float d1 = (j == i1) ? 0.f : fsqrt_ap(fmaxf(S.l.sq1[j], 0.f));
  const float e0 = (j == i0) ? 1.f : ex2_ap(KE * d0);
  const float e1 = (j == i1) ? 1.f : ex2_ap(KE * d1);

  // two interleaved warp-shuffle inclusive scans (double)
  double sc0 = (double)e0, sc1 = (double)e1;
#pragma unroll
  for (int o = 1; o < 32; o <<= 1){
    const double v0 = __shfl_up_sync(0xffffffffu, sc0, o);
    const double v1 = __shfl_up_sync(0xffffffffu, sc1, o);
    if (lane >= o){ sc0 += v0; sc1 += v1; }
  }
  if (lane == 31){ S.l.w0[w] = sc0; S.l.w1[w] = sc1; }
  __syncthreads();
  if (w == 0 && lane < 16){
    double v = S.l.w0[lane];
#pragma unroll
    for (int o = 1; o < 16; o <<= 1){
      const double u = __shfl_up_sync(0xffffu, v, o);
      if (lane >= o) v += u;
    }
    S.l.w0[lane] = v;
  } else if (w == 1 && lane < 16){
    double v = S.l.w1[lane];
#pragma unroll
    for (int o = 1; o < 16; o <<= 1){
      const double u = __shfl_up_sync(0xffffu, v, o);
      if (lane >= o) v += u;
    }
    S.l.w1[lane] = v;
  }
  __syncthreads();
  const double q0 = ((w > 0) ? S.l.w0[w - 1] : 0.0) + sc0;
  const double q1 = ((w > 0) ? S.l.w1[w - 1] : 0.0) + sc1;
  S.l.P0[t] = q0;
  S.l.P1[t] = q1;
  __syncthreads();
  const double total0 = S.l.P0[N - 1], total1 = S.l.P1[N - 1];

  // il: first sorted pos with Ls >= li (label-only, shared by both rows)
  int lo = 0, len = N;
  while (len){ const int h = len >> 1, m = lo + h;
    if (S.l.Ls[m] < li){ lo = m + 1; len -= h + 1; } else len = h; }
  const int il = lo;

  const int k = t;
  const float tk = fabsf(S.l.lab[k & 255] - li);
  int a = 0, la = il + 1, c = il, lc = N - il;
#pragma unroll 1
  for (int s = 0; s < 10; s++){
    if (la){ const int h = la >> 1, m = a + h;
      if (!(fabsf(S.l.Ls[m] - li) < tk)){ a = m + 1; la -= h + 1; } else la = h; }
    if (lc){ const int h = lc >> 1, m = c + h;
      if ( (fabsf(S.l.Ls[m] - li) < tk)){ c = m + 1; lc -= h + 1; } else lc = h; }
  }

  float lgsum = 0.f;
  if (k != i0){
    const double neg = (tk == 0.f) ? (total0 - 1.0)
        : (total0 - (S.l.P0[c - 1] - (a > 0 ? S.l.P0[a - 1] : 0.0)));
    lgsum += lg2_ap((float)neg);
  }
  if (k != i1){
    const double neg = (tk == 0.f) ? (total1 - 1.0)
        : (total1 - (S.l.P1[c - 1] - (a > 0 ? S.l.P1[a - 1] : 0.0)));
    lgsum += lg2_ap((float)neg);
  }

  double acc2 = 0.5 * (double)(d0 + d1) + (double)(LN2 * lgsum);

#pragma unroll
  for (int o = 16; o; o >>= 1) acc2 += __shfl_xor_sync(0xffffffffu, acc2, o);
  if (lane == 0) S.l.red[w] = acc2;
  __syncthreads();

  __shared__ bool s_fin;
  if (w == 0){
    double v = (lane < 16) ? S.l.red[lane] : 0.0;
#pragma unroll
    for (int o = 8; o; o >>= 1) v += __shfl_xor_sync(0xffffffffu, v, o);
    if (lane == 0){
      g_partial[b] = v;
      __threadfence();
      s_fin = (atomicAdd(&g_c3, 1u) == 255u);
    }
  }
  __syncthreads();

  if (s_fin){
    double v = (t < 256) ? *((volatile double*)&g_partial[t]) : 0.0;
#pragma unroll
    for (int o = 16; o; o >>= 1) v += __shfl_xor_sync(0xffffffffu, v, o);
    if (lane == 0) S.l.red[w] = v;
    __syncthreads();
    if (w == 0){
      double s = (lane < 16) ? S.l.red[lane] : 0.0;
#pragma unroll
      for (int o = 8; o; o >>= 1) s += __shfl_xor_sync(0xffffffffu, s, o);
      if (lane == 0){
        out[0] = (float)(s / (512.0 * 511.0));
        g_c3 = 0;
      }
    }
  }
}

extern "C" void kernel_launch(void* const* d_in, const int* in_sizes, int n_in,
                              void* d_out, int out_size)
{
  const float* feat   = (const float*)d_in[0];
  const float* labels = (const float*)d_in[1];
  float* out = (float*)d_out;

  cudaFuncSetAttribute(rnc_all, cudaFuncAttributeMaxDynamicSharedMemorySize,
                       (int)sizeof(USm));
  rnc_all<<<256, 512, sizeof(USm)>>>(feat, labels, out);
}

// round 9
// speedup vs baseline: 1.1733x; 1.1509x over previous
#include <cuda_runtime.h>
#include <math.h>

#define N 512

typedef unsigned long long ull;

__device__ float    g_sq[N * N];
__device__ float    g_Ls[N];
__device__ int      g_perm[N];
__device__ int      g_rank[256];
__device__ double   g_partial[256];
__device__ unsigned g_c1, g_c2, g_c3;   // zero-init; self-resetting

__device__ __forceinline__ int fbase(int i){
  return (i < 256) ? (i * 512) : ((i - 256) * 512 + 256);
}
__device__ __forceinline__ void fma2(ull &acc, ull a, ull b){
  asm("fma.rn.f32x2 %0, %1, %2, %0;" : "+l"(acc) : "l"(a), "l"(b));
}
__device__ __forceinline__ void add2(ull &acc, ull a){
  asm("add.rn.f32x2 %0, %0, %1;" : "+l"(acc) : "l"(a));
}
__device__ __forceinline__ float2 u2f(ull x){
  float2 f; asm("mov.b64 {%0,%1}, %2;" : "=f"(f.x), "=f"(f.y) : "l"(x)); return f;
}
__device__ __forceinline__ ull f2u(float a, float b){
  ull r; asm("mov.b64 %0, {%1,%2};" : "=l"(r) : "f"(a), "f"(b)); return r;
}
__device__ __forceinline__ float fsqrt_ap(float x){
  float r; asm("sqrt.approx.f32 %0, %1;" : "=f"(r) : "f"(x)); return r;
}
__device__ __forceinline__ float ex2_ap(float x){
  float r; asm("ex2.approx.f32 %0, %1;" : "=f"(r) : "f"(x)); return r;
}
__device__ __forceinline__ float lg2_ap(float x){
  float r; asm("lg2.approx.f32 %0, %1;" : "=f"(r) : "f"(x)); return r;
}

struct GS {                     // phase-1 layout
  ull        Au[32][128];       // A tile [row][k-pair]                 32 KB
  ulonglong2 Bv[64][17];        // B tile [kpair-pair][j], padded       17 KB
  float      Cpart[32][33];     // k-split partials                     ~4.2 KB
  float      nrmA[32];
  float      nrmB[32];
  float      lab[256];
  int        rankcnt;
};
struct LS {                     // phase-2 layout (all float)
  float Ls[N];  int perm[N];
  float lab[256];
  float sq0[N], sq1[N];
  ull   pre[N], suf[N];         // packed {row0,row1} prefix/suffix sums
  ull   wf[16], wr[16];
  double red[16];
};
union USm { GS g; LS l; };

__global__ void __launch_bounds__(512, 2) rnc_all(const float* __restrict__ feat,
                                                  const float* __restrict__ labels,
                                                  float* __restrict__ out)
{
  extern __shared__ char raw[];
  USm& S = *(USm*)raw;

  const int t = threadIdx.x, lane = t & 31, w = t >> 5;
  const int b = blockIdx.x;
  const int bj = b & 15, bi = b >> 4;
  const int r0 = bi * 32, j0 = bj * 32;

  // ================= PHASE 1: distances (32x32 Gram tile, k-split) ============
  if (t < 256) S.g.lab[t] = labels[t];
  if (t == 0)  S.g.rankcnt = 0;

#pragma unroll
  for (int p = 0; p < 4; p++){                       // A tile
    const int idx = t + 512 * p;
    const int row = idx >> 6, c = idx & 63;
    ((float4*)S.g.Au[row])[c] = *(const float4*)(feat + fbase(r0 + row) + 4 * c);
  }
  {                                                  // B tile, kpair-pair layout
    const int j = t >> 4, u = t & 15;
#pragma unroll
    for (int p = 0; p < 4; p++){
      const float4 v = *(const float4*)(feat + fbase(j0 + j) + 64 * p + 4 * u);
      S.g.Bv[16 * p + u][j] = make_ulonglong2(f2u(v.x, v.y), f2u(v.z, v.w));
    }
  }
  __syncthreads();

  // distributed label rank of label b
  if (t < 256){
    const float vb = S.g.lab[b];
    const float vt = S.g.lab[t];
    const bool pred = (vt < vb) || ((vt == vb) && (t < b));
    const unsigned bal = __ballot_sync(0xffffffffu, pred);
    if (lane == 0 && bal) atomicAdd(&S.g.rankcnt, __popc(bal));
  }

  // norms
  if (t < 32){
    ull a0 = 0, a1 = 0;
#pragma unroll 16
    for (int d2 = 0; d2 < 128; d2 += 2){
      fma2(a0, S.g.Au[t][d2],   S.g.Au[t][d2]);
      fma2(a1, S.g.Au[t][d2+1], S.g.Au[t][d2+1]);
    }
    const float2 f0 = u2f(a0), f1 = u2f(a1);
    S.g.nrmA[t] = (f0.x + f0.y) + (f1.x + f1.y);
  } else if (t < 64){
    const int jn = t - 32;
    ull a0 = 0, a1 = 0;
#pragma unroll 16
    for (int q = 0; q < 64; q++){
      const ulonglong2 bv = S.g.Bv[q][jn];
      fma2(a0, bv.x, bv.x);
      fma2(a1, bv.y, bv.y);
    }
    const float2 f0 = u2f(a0), f1 = u2f(a1);
    S.g.nrmB[jn] = (f0.x + f0.y) + (f1.x + f1.y);
  }

  // main: warp-half kh covers 32 kpair-pairs, 4 rows per warp, j = lane
  const int w2 = w & 7, kh = w >> 3;
  ull acc[4] = {0, 0, 0, 0};
#pragma unroll 8
  for (int s = 0; s < 32; s++){
    const int q = kh * 32 + s;
    const ulonglong2 bv = S.g.Bv[q][lane];           // LDS.128
#pragma unroll
    for (int rr = 0; rr < 4; rr++){
      const ulonglong2 av = *(const ulonglong2*)&S.g.Au[4*w2 + rr][2*q];  // broadcast
      fma2(acc[rr], av.x, bv.x);
      fma2(acc[rr], av.y, bv.y);
    }
  }
  float p[4];
#pragma unroll
  for (int rr = 0; rr < 4; rr++){ const float2 g = u2f(acc[rr]); p[rr] = g.x + g.y; }
  if (kh == 1){
#pragma unroll
    for (int rr = 0; rr < 4; rr++) S.g.Cpart[4*w2 + rr][lane] = p[rr];
  }
  __syncthreads();

  if (t == 0){
    const int r = S.g.rankcnt;
    const float vb = S.g.lab[b];
    g_Ls[2*r] = vb;   g_Ls[2*r + 1] = vb;
    g_perm[2*r] = b;  g_perm[2*r + 1] = b + 256;
    g_rank[b] = 2*r;
  }
  if (kh == 0){
    const float nj = S.g.nrmB[lane];
#pragma unroll
    for (int rr = 0; rr < 4; rr++){
      const float ni = S.g.nrmA[4*w2 + rr];
      g_sq[(r0 + 4*w2 + rr) * N + j0 + lane] =
          ni + nj - 2.f * (p[rr] + S.g.Cpart[4*w2 + rr][lane]);
    }
  }
  __threadfence();     // make this thread's g_sq writes globally visible
  __syncthreads();

  // ================= GRID BARRIER (all 256 blocks co-resident) ================
  if (t == 0){
    atomicAdd(&g_c1, 1u);
    while (*(volatile unsigned*)&g_c1 < 256u) __nanosleep(64);
    __threadfence();
    if (atomicAdd(&g_c2, 1u) == 255u){ g_c1 = 0u; g_c2 = 0u; __threadfence(); }
  }
  __syncthreads();     // also separates the smem union phases

  // ================= PHASE 2: loss for rows b and b+256 =======================
  const int i0 = b;
  if (t < 256) S.l.lab[t] = labels[t];
  S.l.Ls[t]   = __ldcg(&g_Ls[t]);
  S.l.perm[t] = __ldcg(&g_perm[t]);
  S.l.sq0[t]  = __ldcg(&g_sq[i0 * N + t]);
  S.l.sq1[t]  = __ldcg(&g_sq[(i0 + 256) * N + t]);
  __syncthreads();

  const int   il  = __ldcg(&g_rank[b]);   // sorted position of li's pair
  const float li  = S.l.lab[b];
  const float KE  = -0.72134752044448170f;   // -0.5 * log2(e)
  const float LN2 =  0.69314718055994531f;

  const int y = t;                 // sorted position handled by this thread
  const int j = S.l.perm[y];
  const float d0 = (y == il    ) ? 0.f : fsqrt_ap(fmaxf(S.l.sq0[j], 0.f));
  const float d1 = (y == il + 1) ? 0.f : fsqrt_ap(fmaxf(S.l.sq1[j], 0.f));
  const float e0 = (y == il    ) ? 1.f : ex2_ap(KE * d0);
  const float e1 = (y == il + 1) ? 1.f : ex2_ap(KE * d1);

  // packed forward(prefix) + reverse(suffix) inclusive scans, rows {0,1} per ull
  ull pf = f2u(e0, e1), pr = pf;
#pragma unroll
  for (int o = 1; o < 32; o <<= 1){
    const ull vf = __shfl_up_sync  (0xffffffffu, pf, o);
    const ull vr = __shfl_down_sync(0xffffffffu, pr, o);
    if (lane >= o)      add2(pf, vf);
    if (lane + o < 32)  add2(pr, vr);
  }
  if (lane == 31) S.l.wf[w] = pf;
  if (lane == 0)  S.l.wr[w] = pr;
  __syncthreads();
  if (w == 0 && lane < 16){
    ull v = S.l.wf[lane];
#pragma unroll
    for (int o = 1; o < 16; o <<= 1){
      const ull u = __shfl_up_sync(0xffffu, v, o);
      if (lane >= o) add2(v, u);
    }
    S.l.wf[lane] = v;
  } else if (w == 1 && lane < 16){
    ull v = S.l.wr[lane];
#pragma unroll
    for (int o = 1; o < 16; o <<= 1){
      const ull u = __shfl_down_sync(0xffffu, v, o);
      if (lane + o < 16) add2(v, u);
    }
    S.l.wr[lane] = v;
  }
  __syncthreads();
  { ull v = pf; if (w > 0)  add2(v, S.l.wf[w - 1]); S.l.pre[y] = v; }
  { ull v = pr; if (w < 15) add2(v, S.l.wr[w + 1]); S.l.suf[y] = v; }
  __syncthreads();

  const float2 total = u2f(S.l.pre[N - 1]);
  const float  lv = S.l.Ls[y];

  float lg = 0.f;
  if (y == il){                        // k = i0: row0 diag skip; row1 tk==0
    lg  = lg2_ap(total.y - 1.f);
  } else if (y == il + 1){             // k = i1: row1 diag skip; row0 tk==0
    lg  = lg2_ap(total.x - 1.f);
  } else {
    const float tk = fabsf(lv - li);
    int a, c;
    if (y > il){                       // lv > li: right boundary free (pair start)
      c = y & ~1;
      int lo = 0, len = il + 1;        // first m in [0, il] with |Ls[m]-li| < tk
      while (len){ const int h = len >> 1, m = lo + h;
        if (!(fabsf(S.l.Ls[m] - li) < tk)){ lo = m + 1; len -= h + 1; } else len = h; }
      a = lo;
    } else {                           // lv < li: left boundary free (past pair)
      a = (y | 1) + 1;
      int lo = il, len = N - il;       // first m in [il, N) with |Ls[m]-li| >= tk
      while (len){ const int h = len >> 1, m = lo + h;
        if (fabsf(S.l.Ls[m] - li) < tk){ lo = m + 1; len -= h + 1; } else len = h; }
      c = lo;
    }
    float2 PA = make_float2(0.f, 0.f), SC = make_float2(0.f, 0.f);
    if (a > 0) PA = u2f(S.l.pre[a - 1]);
    if (c < N) SC = u2f(S.l.suf[c]);
    lg = lg2_ap(PA.x + SC.x) + lg2_ap(PA.y + SC.y);   // neg = pre + suf, no cancellation
  }

  double acc2 = 0.5 * (double)(d0 + d1) + (double)LN2 * (double)lg;

#pragma unroll
  for (int o = 16; o; o >>= 1) acc2 += __shfl_xor_sync(0xffffffffu, acc2, o);
  if (lane == 0) S.l.red[w] = acc2;
  __syncthreads();

  __shared__ bool s_fin;
  if (w == 0){
    double v = (lane < 16) ? S.l.red[lane] : 0.0;
#pragma unroll
    for (int o = 8; o; o >>= 1) v += __shfl_xor_sync(0xffffffffu, v, o);
    if (lane == 0){
      g_partial[b] = v;
      __threadfence();
      s_fin = (atomicAdd(&g_c3, 1u) == 255u);
    }
  }
  __syncthreads();

  if (s_fin){
    double v = (t < 256) ? *((volatile double*)&g_partial[t]) : 0.0;
#pragma unroll
    for (int o = 16; o; o >>= 1) v += __shfl_xor_sync(0xffffffffu, v, o);
    if (lane == 0) S.l.red[w] = v;
    __syncthreads();
    if (w == 0){
      double s = (lane < 16) ? S.l.red[lane] : 0.0;
#pragma unroll
      for (int o = 8; o; o >>= 1) s += __shfl_xor_sync(0xffffffffu, s, o);
      if (lane == 0){
        out[0] = (float)(s / (512.0 * 511.0));
        g_c3 = 0;
      }
    }
  }
}

extern "C" void kernel_launch(void* const* d_in, const int* in_sizes, int n_in,
                              void* d_out, int out_size)
{
  const float* feat   = (const float*)d_in[0];
  const float* labels = (const float*)d_in[1];
  float* out = (float*)d_out;

  cudaFuncSetAttribute(rnc_all, cudaFuncAttributeMaxDynamicSharedMemorySize,
                       (int)sizeof(USm));
  rnc_all<<<256, 512, sizeof(USm)>>>(feat, labels, out);
}

// round 10
// speedup vs baseline: 1.3819x; 1.1778x over previous
#include <cuda_runtime.h>
#include <math.h>

#define N 512

typedef unsigned long long ull;

__device__ float    g_sq[N * N];
__device__ float    g_Ls[N];
__device__ int      g_perm[N];
__device__ int      g_rank[256];
__device__ double   g_partial[256];
__device__ unsigned g_c1, g_c2, g_c3;   // zero-init; self-resetting

__device__ __forceinline__ int fbase(int i){
  return (i < 256) ? (i * 512) : ((i - 256) * 512 + 256);
}
__device__ __forceinline__ void fma2(ull &acc, ull a, ull b){
  asm("fma.rn.f32x2 %0, %1, %2, %0;" : "+l"(acc) : "l"(a), "l"(b));
}
__device__ __forceinline__ void add2(ull &acc, ull a){
  asm("add.rn.f32x2 %0, %0, %1;" : "+l"(acc) : "l"(a));
}
__device__ __forceinline__ float2 u2f(ull x){
  float2 f; asm("mov.b64 {%0,%1}, %2;" : "=f"(f.x), "=f"(f.y) : "l"(x)); return f;
}
__device__ __forceinline__ ull f2u(float a, float b){
  ull r; asm("mov.b64 %0, {%1,%2};" : "=l"(r) : "f"(a), "f"(b)); return r;
}
__device__ __forceinline__ float fsqrt_ap(float x){
  float r; asm("sqrt.approx.f32 %0, %1;" : "=f"(r) : "f"(x)); return r;
}
__device__ __forceinline__ float ex2_ap(float x){
  float r; asm("ex2.approx.f32 %0, %1;" : "=f"(r) : "f"(x)); return r;
}
__device__ __forceinline__ float lg2_ap(float x){
  float r; asm("lg2.approx.f32 %0, %1;" : "=f"(r) : "f"(x)); return r;
}

struct GS {                       // phase-1 layout
  ulonglong2 Bv[64][17];          // B tile [kpair-pair][j]          17408 B
  ull        Au[32][128];         // A tile (off-diag uses rows 0-15) 32768 B
  float      Cp4[4][16][33];      // off-diag 4-way k-split partials  8448 B
  float      CpD[32][33];         // diag 2-way k-split partials      4224 B
  float      nrmA[32];
  float      nrmB[32];
};
struct LS {                       // phase-2 layout (all float scans)
  float Ls[N];  int perm[N];
  float sq0[N], sq1[N];
  ull   pre[N], suf[N];           // packed {row0,row1} prefix/suffix sums
  ull   wf[16], wrv[16];
  double red[16];
};
union USm { GS g; LS l; };

__global__ void __launch_bounds__(512, 2) rnc_all(const float* __restrict__ feat,
                                                  const float* __restrict__ labels,
                                                  float* __restrict__ out)
{
  extern __shared__ char raw[];
  USm& S = *(USm*)raw;
  __shared__ float s_lab[256];
  __shared__ int   s_rankcnt;
  __shared__ bool  s_fin;

  const int t = threadIdx.x, lane = t & 31, w = t >> 5;
  const int b = blockIdx.x;

  // tile assignment: 240 half off-diagonal tiles + 16 diagonal tiles
  int bi, bj, half;
  if (b < 240){
    int p = b >> 1; half = b & 1;
    bi = 0;
    while (p >= 15 - bi){ p -= 15 - bi; bi++; }
    bj = bi + 1 + p;
  } else { bi = bj = b - 240; half = 0; }
  const int j0 = bj * 32;
  const int r0 = bi * 32 + ((b < 240) ? 16 * half : 0);
  const int nrows = (b < 240) ? 16 : 32;

  // ================= PHASE 1 =================================================
  if (t < 256) s_lab[t] = labels[t];
  if (t == 0)  s_rankcnt = 0;

  // A tile [nrows][256 k] natural layout (k-pairs in ull halves)
  if (b < 240){
#pragma unroll
    for (int p2 = 0; p2 < 2; p2++){
      const int idx = t + 512 * p2;           // 0..1023
      const int row = idx >> 6, c = idx & 63;
      ((float4*)S.g.Au[row])[c] = *(const float4*)(feat + fbase(r0 + row) + 4 * c);
    }
  } else {
#pragma unroll
    for (int p2 = 0; p2 < 4; p2++){
      const int idx = t + 512 * p2;           // 0..2047
      const int row = idx >> 6, c = idx & 63;
      ((float4*)S.g.Au[row])[c] = *(const float4*)(feat + fbase(r0 + row) + 4 * c);
    }
  }
  // B tile (32 js), kpair-pair layout
  {
    const int j = t >> 4, u = t & 15;
#pragma unroll
    for (int p2 = 0; p2 < 4; p2++){
      const float4 v = *(const float4*)(feat + fbase(j0 + j) + 64 * p2 + 4 * u);
      S.g.Bv[16 * p2 + u][j] = make_ulonglong2(f2u(v.x, v.y), f2u(v.z, v.w));
    }
  }
  __syncthreads();

  // distributed label rank of label b
  if (t < 256){
    const float vb = s_lab[b];
    const float vt = s_lab[t];
    const bool pred = (vt < vb) || ((vt == vb) && (t < b));
    const unsigned bal = __ballot_sync(0xffffffffu, pred);
    if (lane == 0 && bal) atomicAdd(&s_rankcnt, __popc(bal));
  }

  // norms
  if (t < nrows){
    ull a0 = 0, a1 = 0;
#pragma unroll 16
    for (int d2 = 0; d2 < 128; d2 += 2){
      fma2(a0, S.g.Au[t][d2],   S.g.Au[t][d2]);
      fma2(a1, S.g.Au[t][d2+1], S.g.Au[t][d2+1]);
    }
    const float2 f0 = u2f(a0), f1 = u2f(a1);
    S.g.nrmA[t] = (f0.x + f0.y) + (f1.x + f1.y);
  } else if (t >= 32 && t < 64){
    const int jn = t - 32;
    ull a0 = 0, a1 = 0;
#pragma unroll 16
    for (int q = 0; q < 64; q++){
      const ulonglong2 bv = S.g.Bv[q][jn];
      fma2(a0, bv.x, bv.x);
      fma2(a1, bv.y, bv.y);
    }
    const float2 f0 = u2f(a0), f1 = u2f(a1);
    S.g.nrmB[jn] = (f0.x + f0.y) + (f1.x + f1.y);
  }

  // main Gram loops
  float pd[4];                 // diag-path partials kept across sync
  const int w2 = w & 7, kh = w >> 3;
  if (b < 240){
    const int wr = w & 3, kq = w >> 2;      // 4 rows x k-quarter per warp
    ull acc[4] = {0, 0, 0, 0};
#pragma unroll
    for (int s = 0; s < 16; s++){
      const int q = kq * 16 + s;
      const ulonglong2 bv = S.g.Bv[q][lane];
#pragma unroll
      for (int rr = 0; rr < 4; rr++){
        const ulonglong2 av = *(const ulonglong2*)&S.g.Au[4*wr + rr][2*q];  // broadcast
        fma2(acc[rr], av.x, bv.x);
        fma2(acc[rr], av.y, bv.y);
      }
    }
#pragma unroll
    for (int rr = 0; rr < 4; rr++){
      const float2 g = u2f(acc[rr]);
      S.g.Cp4[kq][4*wr + rr][lane] = g.x + g.y;
    }
  } else {
    ull acc[4] = {0, 0, 0, 0};
#pragma unroll 8
    for (int s = 0; s < 32; s++){
      const int q = kh * 32 + s;
      const ulonglong2 bv = S.g.Bv[q][lane];
#pragma unroll
      for (int rr = 0; rr < 4; rr++){
        const ulonglong2 av = *(const ulonglong2*)&S.g.Au[4*w2 + rr][2*q];  // broadcast
        fma2(acc[rr], av.x, bv.x);
        fma2(acc[rr], av.y, bv.y);
      }
    }
#pragma unroll
    for (int rr = 0; rr < 4; rr++){ const float2 g = u2f(acc[rr]); pd[rr] = g.x + g.y; }
    if (kh == 1){
#pragma unroll
      for (int rr = 0; rr < 4; rr++) S.g.CpD[4*w2 + rr][lane] = pd[rr];
    }
  }
  __syncthreads();

  if (t == 0){
    const int r = s_rankcnt;
    const float vb = s_lab[b];
    g_Ls[2*r] = vb;   g_Ls[2*r + 1] = vb;
    g_perm[2*r] = b;  g_perm[2*r + 1] = b + 256;
    g_rank[b] = 2*r;
  }

  // epilogue: sq = ni + nj - 2g ; mirror write for off-diag tiles
  if (b < 240){
    const int row = t >> 5, col = t & 31;   // 16 x 32 outputs, 1 per thread
    const float gsum = S.g.Cp4[0][row][col] + S.g.Cp4[1][row][col]
                     + S.g.Cp4[2][row][col] + S.g.Cp4[3][row][col];
    const float sq = S.g.nrmA[row] + S.g.nrmB[col] - 2.f * gsum;
    const int gi = r0 + row, gj = j0 + col;
    g_sq[gi * N + gj] = sq;
    g_sq[gj * N + gi] = sq;
  } else if (kh == 0){
    const float nj = S.g.nrmB[lane];
#pragma unroll
    for (int rr = 0; rr < 4; rr++){
      const float ni = S.g.nrmA[4*w2 + rr];
      g_sq[(r0 + 4*w2 + rr) * N + j0 + lane] =
          ni + nj - 2.f * (pd[rr] + S.g.CpD[4*w2 + rr][lane]);
    }
  }
  __syncthreads();

  // ================= GRID BARRIER (all 256 blocks co-resident) ================
  if (t == 0){
    __threadfence();
    atomicAdd(&g_c1, 1u);
    while (*(volatile unsigned*)&g_c1 < 256u) __nanosleep(64);
    __threadfence();
    if (atomicAdd(&g_c2, 1u) == 255u){ g_c1 = 0u; g_c2 = 0u; __threadfence(); }
  }
  __syncthreads();     // also separates the smem union phases

  // ================= PHASE 2: loss for rows b and b+256 =======================
  S.l.Ls[t]   = __ldcg(&g_Ls[t]);
  S.l.perm[t] = __ldcg(&g_perm[t]);
  S.l.sq0[t]  = __ldcg(&g_sq[b * N + t]);
  S.l.sq1[t]  = __ldcg(&g_sq[(b + 256) * N + t]);
  __syncthreads();

  const int   il  = __ldcg(&g_rank[b]);      // sorted position of li's pair
  const float li  = s_lab[b];
  const float KE  = -0.72134752044448170f;   // -0.5 * log2(e)
  const float LN2 =  0.69314718055994531f;

  const int y = t;                 // sorted position handled by this thread
  const int j = S.l.perm[y];
  const float d0 = (y == il    ) ? 0.f : fsqrt_ap(fmaxf(S.l.sq0[j], 0.f));
  const float d1 = (y == il + 1) ? 0.f : fsqrt_ap(fmaxf(S.l.sq1[j], 0.f));
  const float e0 = (y == il    ) ? 1.f : ex2_ap(KE * d0);
  const float e1 = (y == il + 1) ? 1.f : ex2_ap(KE * d1);

  // packed forward(prefix) + reverse(suffix) inclusive scans, rows {0,1} per ull
  ull pf = f2u(e0, e1), pr = pf;
#pragma unroll
  for (int o = 1; o < 32; o <<= 1){
    const ull vf = __shfl_up_sync  (0xffffffffu, pf, o);
    const ull vr = __shfl_down_sync(0xffffffffu, pr, o);
    if (lane >= o)      add2(pf, vf);
    if (lane + o < 32)  add2(pr, vr);
  }
  if (lane == 31) S.l.wf[w]  = pf;
  if (lane == 0)  S.l.wrv[w] = pr;
  __syncthreads();
  if (w == 0 && lane < 16){
    ull v = S.l.wf[lane];
#pragma unroll
    for (int o = 1; o < 16; o <<= 1){
      const ull u = __shfl_up_sync(0xffffu, v, o);
      if (lane >= o) add2(v, u);
    }
    S.l.wf[lane] = v;
  } else if (w == 1 && lane < 16){
    ull v = S.l.wrv[lane];
#pragma unroll
    for (int o = 1; o < 16; o <<= 1){
      const ull u = __shfl_down_sync(0xffffu, v, o);
      if (lane + o < 16) add2(v, u);
    }
    S.l.wrv[lane] = v;
  }
  __syncthreads();
  { ull v = pf; if (w > 0)  add2(v, S.l.wf[w - 1]);  S.l.pre[y] = v; }
  { ull v = pr; if (w < 15) add2(v, S.l.wrv[w + 1]); S.l.suf[y] = v; }
  __syncthreads();

  const float2 total = u2f(S.l.pre[N - 1]);
  const float  lv = S.l.Ls[y];

  float lg = 0.f;
  if (y == il){                        // k = i0: row0 diag skip; row1 tk==0
    lg = lg2_ap(total.y - 1.f);
  } else if (y == il + 1){             // k = i1: row1 diag skip; row0 tk==0
    lg = lg2_ap(total.x - 1.f);
  } else {
    const float tk = fabsf(lv - li);
    int a, c;
    if (y > il){                       // lv > li: right boundary free (pair start)
      c = y & ~1;
      int lo = 0, len = il + 1;        // first m in [0, il] with |Ls[m]-li| < tk
      while (len){ const int h = len >> 1, m = lo + h;
        if (!(fabsf(S.l.Ls[m] - li) < tk)){ lo = m + 1; len -= h + 1; } else len = h; }
      a = lo;
    } else {                           // lv < li: left boundary free (past pair)
      a = (y | 1) + 1;
      int lo = il, len = N - il;       // first m in [il, N) with |Ls[m]-li| >= tk
      while (len){ const int h = len >> 1, m = lo + h;
        if (fabsf(S.l.Ls[m] - li) < tk){ lo = m + 1; len -= h + 1; } else len = h; }
      c = lo;
    }
    float2 PA = make_float2(0.f, 0.f), SC = make_float2(0.f, 0.f);
    if (a > 0) PA = u2f(S.l.pre[a - 1]);
    if (c < N) SC = u2f(S.l.suf[c]);
    lg = lg2_ap(PA.x + SC.x) + lg2_ap(PA.y + SC.y);   // neg = pre + suf
  }

  double acc2 = 0.5 * (double)(d0 + d1) + (double)LN2 * (double)lg;

#pragma unroll
  for (int o = 16; o; o >>= 1) acc2 += __shfl_xor_sync(0xffffffffu, acc2, o);
  if (lane == 0) S.l.red[w] = acc2;
  __syncthreads();

  if (w == 0){
    double v = (lane < 16) ? S.l.red[lane] : 0.0;
#pragma unroll
    for (int o = 8; o; o >>= 1) v += __shfl_xor_sync(0xffffffffu, v, o);
    if (lane == 0){
      g_partial[b] = v;
      __threadfence();
      s_fin = (atomicAdd(&g_c3, 1u) == 255u);
    }
  }
  __syncthreads();

  if (s_fin){
    double v = (t < 256) ? *((volatile double*)&g_partial[t]) : 0.0;
#pragma unroll
    for (int o = 16; o; o >>= 1) v += __shfl_xor_sync(0xffffffffu, v, o);
    if (lane == 0) S.l.red[w] = v;
    __syncthreads();
    if (w == 0){
      double s = (lane < 16) ? S.l.red[lane] : 0.0;
#pragma unroll
      for (int o = 8; o; o >>= 1) s += __shfl_xor_sync(0xffffffffu, s, o);
      if (lane == 0){
        out[0] = (float)(s / (512.0 * 511.0));
        g_c3 = 0;
      }
    }
  }
}

extern "C" void kernel_launch(void* const* d_in, const int* in_sizes, int n_in,
                              void* d_out, int out_size)
{
  const float* feat   = (const float*)d_in[0];
  const float* labels = (const float*)d_in[1];
  float* out = (float*)d_out;

  cudaFuncSetAttribute(rnc_all, cudaFuncAttributeMaxDynamicSharedMemorySize,
                       (int)sizeof(USm));
  rnc_all<<<256, 512, sizeof(USm)>>>(feat, labels, out);
}